// round 1
// baseline (speedup 1.0000x reference)
#include <cuda_runtime.h>
#include <math.h>
#include <stdint.h>

#define MAXN 8192
#define NMS_SMEM (MAXN * 8 + MAXN * 16 + MAXN)  // keys(64K) + boxes(128K) + keep(8K) = 200KB

__device__ float4 g_boxes[MAXN];
__device__ unsigned long long g_keys[MAXN];
__device__ int g_count;

__global__ void k_reset() { g_count = 0; }

// Per-box preprocessing: scale/mask, xyxy, round; compact valid keys; zero output.
__global__ void k_prep(const float* __restrict__ o0, const float* __restrict__ o1,
                       int P0, int P1, float* __restrict__ out, int out_size, int N) {
    int n = blockIdx.x * blockDim.x + threadIdx.x;
    int stride = gridDim.x * blockDim.x;
    for (int t = n; t < out_size; t += stride) out[t] = 0.0f;
    if (n >= N) return;

    const float* src;
    int P, loc;
    int A0 = P0 * P0;
    if (n < A0) { src = o0; P = P0; loc = n; }
    else        { src = o1; P = P1; loc = n - A0; }
    int i = loc / P, j = loc - i * P;
    int A = P * P;

    float prob = src[0 * A + loc];
    float x1   = src[1 * A + loc];
    float x2   = src[2 * A + loc];
    float x3   = src[3 * A + loc];
    float x4   = src[4 * A + loc];

    float xps = 640.0f / (float)P;   // exact: 16 or 8
    float yps = 480.0f / (float)P;   // exact: 12 or 6
    bool m = prob > 0.9f;

    float c1 = m ? (x1 * xps + (float)i * xps) : x1;
    float c2 = m ? (x2 * yps + (float)j * yps) : x2;
    float c3 = m ? (x3 * 640.0f) : x3;
    float c4 = m ? (x4 * 480.0f) : x4;

    float X1 = rintf(c1);
    float Y1 = rintf(c2);
    float X2 = rintf(c3 + c1);
    float Y2 = rintf(c4 + c2);

    g_boxes[n] = make_float4(X1, Y1, X2, Y2);

    if (m) {
        int pos = atomicAdd(&g_count, 1);
        unsigned int hi = 0xFFFFFFFFu - __float_as_uint(prob);  // descending score
        g_keys[pos] = ((unsigned long long)hi << 32) | (unsigned int)n; // tie: asc index
    }
}

// Single-block: bitonic sort of valid keys, greedy NMS, write kept rows.
extern __shared__ unsigned char smem_raw[];
__global__ void __launch_bounds__(1024, 1) k_sortnms(float* __restrict__ out) {
    unsigned long long* keys = (unsigned long long*)smem_raw;
    float4* sb = (float4*)(smem_raw + MAXN * 8);
    unsigned char* kp = (unsigned char*)(smem_raw + MAXN * 8 + MAXN * 16);

    const int tid = threadIdx.x;
    const int bd  = blockDim.x;

    int M = g_count;
    if (M > MAXN) M = MAXN;
    int P2 = 1;
    while (P2 < M) P2 <<= 1;

    for (int t = tid; t < P2; t += bd)
        keys[t] = (t < M) ? g_keys[t] : 0xFFFFFFFFFFFFFFFFull;
    __syncthreads();

    // Bitonic sort, ascending (key encodes descending score)
    for (int k = 2; k <= P2; k <<= 1) {
        for (int j = k >> 1; j > 0; j >>= 1) {
            for (int t = tid; t < P2; t += bd) {
                int ixj = t ^ j;
                if (ixj > t) {
                    unsigned long long a = keys[t], b = keys[ixj];
                    bool up = ((t & k) == 0);
                    if ((a > b) == up) { keys[t] = b; keys[ixj] = a; }
                }
            }
            __syncthreads();
        }
    }

    // Gather boxes in sorted order
    for (int s = tid; s < M; s += bd) {
        unsigned long long kk = keys[s];
        sb[s] = g_boxes[(unsigned int)kk];
        kp[s] = 1;
    }
    __syncthreads();

    // Greedy NMS. Barrier only on kept iterations (writes only happen there;
    // between barriers kp is constant so the broadcast read is consistent).
    for (int i = 0; i < M - 1; ++i) {
        if (kp[i]) {
            float4 bi = sb[i];
            float ai = (bi.z - bi.x) * (bi.w - bi.y);
            for (int jj = i + 1 + tid; jj < M; jj += bd) {
                if (!kp[jj]) continue;
                float4 bj = sb[jj];
                float iw = fminf(bi.z, bj.z) - fmaxf(bi.x, bj.x);
                float ih = fminf(bi.w, bj.w) - fmaxf(bi.y, bj.y);
                iw = fmaxf(iw, 0.0f);
                ih = fmaxf(ih, 0.0f);
                float inter = iw * ih;
                float aj = (bj.z - bj.x) * (bj.w - bj.y);
                float uni = ai + aj - inter;
                // all quantities are exact integers/half-integers in fp32:
                // inter/uni > 0.5  <=>  inter > 0.5*uni   (exact)
                if (uni > 0.0f && inter > 0.5f * uni) kp[jj] = 0;
            }
            __syncthreads();
        }
    }

    // Emit kept rows: [score, x1, y1, x2-x1, y2-y1]; rest stays zero.
    for (int s = tid; s < M; s += bd) {
        if (kp[s]) {
            unsigned long long kk = keys[s];
            float score = __uint_as_float(0xFFFFFFFFu - (unsigned int)(kk >> 32));
            float4 b = sb[s];
            float* o = out + 5 * s;
            o[0] = score;
            o[1] = b.x;
            o[2] = b.y;
            o[3] = b.z - b.x;
            o[4] = b.w - b.y;
        }
    }
}

extern "C" void kernel_launch(void* const* d_in, const int* in_sizes, int n_in,
                              void* d_out, int out_size) {
    const float* o0 = (const float*)d_in[0];
    const float* o1 = (const float*)d_in[1];
    int P0 = (int)lround(sqrt((double)in_sizes[0] / 5.0));
    int P1 = (int)lround(sqrt((double)in_sizes[1] / 5.0));
    int N = P0 * P0 + P1 * P1;
    float* out = (float*)d_out;

    cudaFuncSetAttribute(k_sortnms, cudaFuncAttributeMaxDynamicSharedMemorySize, NMS_SMEM);

    k_reset<<<1, 1>>>();
    int blocks = (N + 255) / 256;
    k_prep<<<blocks, 256>>>(o0, o1, P0, P1, out, out_size, N);
    k_sortnms<<<1, 1024, NMS_SMEM>>>(out);
}

// round 2
// speedup vs baseline: 1.0064x; 1.0064x over previous
#include <cuda_runtime.h>
#include <math.h>
#include <stdint.h>

#define MAXN 8192
#define NMS_SMEM (MAXN * 8 + MAXN * 16 + MAXN)  // keys(64K) + boxes(128K) + keep(8K) = 200KB

__device__ float4 g_boxes[MAXN];
__device__ unsigned long long g_keys[MAXN];
__device__ int g_count;

__global__ void k_reset() { g_count = 0; }

// Per-box preprocessing: scale/mask, xyxy, round; compact valid keys; zero output.
__global__ void k_prep(const float* __restrict__ o0, const float* __restrict__ o1,
                       int P0, int P1, float* __restrict__ out, int out_size, int N) {
    int n = blockIdx.x * blockDim.x + threadIdx.x;
    int stride = gridDim.x * blockDim.x;
    for (int t = n; t < out_size; t += stride) out[t] = 0.0f;
    if (n >= N) return;

    const float* src;
    int P, loc;
    int A0 = P0 * P0;
    if (n < A0) { src = o0; P = P0; loc = n; }
    else        { src = o1; P = P1; loc = n - A0; }
    int i = loc / P, j = loc - i * P;
    int A = P * P;

    float prob = src[0 * A + loc];
    float x1   = src[1 * A + loc];
    float x2   = src[2 * A + loc];
    float x3   = src[3 * A + loc];
    float x4   = src[4 * A + loc];

    float xps = 640.0f / (float)P;   // exact: 16 or 8
    float yps = 480.0f / (float)P;   // exact: 12 or 6
    bool m = prob > 0.9f;

    float c1 = m ? (x1 * xps + (float)i * xps) : x1;
    float c2 = m ? (x2 * yps + (float)j * yps) : x2;
    float c3 = m ? (x3 * 640.0f) : x3;
    float c4 = m ? (x4 * 480.0f) : x4;

    float X1 = rintf(c1);
    float Y1 = rintf(c2);
    float X2 = rintf(c3 + c1);
    float Y2 = rintf(c4 + c2);

    g_boxes[n] = make_float4(X1, Y1, X2, Y2);

    if (m) {
        int pos = atomicAdd(&g_count, 1);
        unsigned int hi = 0xFFFFFFFFu - __float_as_uint(prob);  // descending score
        g_keys[pos] = ((unsigned long long)hi << 32) | (unsigned int)n; // tie: asc index
    }
}

// Single-block: bitonic sort of valid keys, greedy NMS, write kept rows.
extern __shared__ unsigned char smem_raw[];
__global__ void __launch_bounds__(1024, 1) k_sortnms(float* __restrict__ out) {
    unsigned long long* keys = (unsigned long long*)smem_raw;
    float4* sb = (float4*)(smem_raw + MAXN * 8);
    unsigned char* kp = (unsigned char*)(smem_raw + MAXN * 8 + MAXN * 16);

    const int tid = threadIdx.x;
    const int bd  = blockDim.x;

    int M = g_count;
    if (M > MAXN) M = MAXN;
    int P2 = 1;
    while (P2 < M) P2 <<= 1;

    for (int t = tid; t < P2; t += bd)
        keys[t] = (t < M) ? g_keys[t] : 0xFFFFFFFFFFFFFFFFull;
    __syncthreads();

    // Bitonic sort, ascending (key encodes descending score)
    for (int k = 2; k <= P2; k <<= 1) {
        for (int j = k >> 1; j > 0; j >>= 1) {
            for (int t = tid; t < P2; t += bd) {
                int ixj = t ^ j;
                if (ixj > t) {
                    unsigned long long a = keys[t], b = keys[ixj];
                    bool up = ((t & k) == 0);
                    if ((a > b) == up) { keys[t] = b; keys[ixj] = a; }
                }
            }
            __syncthreads();
        }
    }

    // Gather boxes in sorted order
    for (int s = tid; s < M; s += bd) {
        unsigned long long kk = keys[s];
        sb[s] = g_boxes[(unsigned int)kk];
        kp[s] = 1;
    }
    __syncthreads();

    // Greedy NMS. Barrier only on kept iterations (writes only happen there;
    // between barriers kp is constant so the broadcast read is consistent).
    for (int i = 0; i < M - 1; ++i) {
        if (kp[i]) {
            float4 bi = sb[i];
            float ai = (bi.z - bi.x) * (bi.w - bi.y);
            for (int jj = i + 1 + tid; jj < M; jj += bd) {
                if (!kp[jj]) continue;
                float4 bj = sb[jj];
                float iw = fminf(bi.z, bj.z) - fmaxf(bi.x, bj.x);
                float ih = fminf(bi.w, bj.w) - fmaxf(bi.y, bj.y);
                iw = fmaxf(iw, 0.0f);
                ih = fmaxf(ih, 0.0f);
                float inter = iw * ih;
                float aj = (bj.z - bj.x) * (bj.w - bj.y);
                float uni = ai + aj - inter;
                // all quantities are exact integers/half-integers in fp32:
                // inter/uni > 0.5  <=>  inter > 0.5*uni   (exact)
                if (uni > 0.0f && inter > 0.5f * uni) kp[jj] = 0;
            }
            __syncthreads();
        }
    }

    // Emit kept rows: [score, x1, y1, x2-x1, y2-y1]; rest stays zero.
    for (int s = tid; s < M; s += bd) {
        if (kp[s]) {
            unsigned long long kk = keys[s];
            float score = __uint_as_float(0xFFFFFFFFu - (unsigned int)(kk >> 32));
            float4 b = sb[s];
            float* o = out + 5 * s;
            o[0] = score;
            o[1] = b.x;
            o[2] = b.y;
            o[3] = b.z - b.x;
            o[4] = b.w - b.y;
        }
    }
}

extern "C" void kernel_launch(void* const* d_in, const int* in_sizes, int n_in,
                              void* d_out, int out_size) {
    const float* o0 = (const float*)d_in[0];
    const float* o1 = (const float*)d_in[1];
    int P0 = (int)lround(sqrt((double)in_sizes[0] / 5.0));
    int P1 = (int)lround(sqrt((double)in_sizes[1] / 5.0));
    int N = P0 * P0 + P1 * P1;
    float* out = (float*)d_out;

    cudaFuncSetAttribute(k_sortnms, cudaFuncAttributeMaxDynamicSharedMemorySize, NMS_SMEM);

    k_reset<<<1, 1>>>();
    int blocks = (N + 255) / 256;
    k_prep<<<blocks, 256>>>(o0, o1, P0, P1, out, out_size, N);
    k_sortnms<<<1, 1024, NMS_SMEM>>>(out);
}